// round 2
// baseline (speedup 1.0000x reference)
#include <cuda_runtime.h>
#include <cuda_bf16.h>
#include <cstdint>

// ---------------------------------------------------------------------------
// Problem constants (fixed shapes from reference)
// ---------------------------------------------------------------------------
#define A_TOT 20000
#define L_TOT 80000
#define N_TOT 100000
#define E_AA  400000
#define E_AL  800000
#define ETOT  (E_AA + 2 * E_AL)   // 2,000,000 directed edges (no self loops)
#define HDIM  64
#define BN_EPS 1e-5f

// ---------------------------------------------------------------------------
// Scratch (device globals: allocation-free rule)
// ---------------------------------------------------------------------------
__device__ float g_x[N_TOT * HDIM];     // node features (LSTM outputs)
__device__ float g_h[N_TOT * HDIM];     // lin output (pre-aggregation)
__device__ float g_out1[N_TOT * HDIM];  // conv1 output
__device__ float g_deg[N_TOT];
__device__ float g_dinv[N_TOT];
__device__ float g_stats[256];          // [0:64) sum, [64:128) sumsq, [128:192) scale, [192:256) shift

// ---------------------------------------------------------------------------
// Fast math helpers
// ---------------------------------------------------------------------------
__device__ __forceinline__ float sigmoidf_(float x) {
    return 1.0f / (1.0f + __expf(-x));
}
__device__ __forceinline__ float tanhf_(float x) {
    // tanh(x) = 2*sigmoid(2x) - 1 ; saturates correctly at +-inf
    return 2.0f / (1.0f + __expf(-2.0f * x)) - 1.0f;
}

// ---------------------------------------------------------------------------
// LSTM kernel: 1 warp handles 4 rows; WhhT in shared (pad 257, conflict-free)
// Gate layout j = lane + 32*i : i gates {0,1}=i, {2,3}=f, {4,5}=g, {6,7}=o
// ---------------------------------------------------------------------------
template <int T, int D, bool MEAN>
__global__ __launch_bounds__(256)
void lstm_kernel(const float* __restrict__ xin,   // [N, T, D]
                 const float* __restrict__ Wih,   // [256, D]
                 const float* __restrict__ Whh,   // [256, 64]
                 const float* __restrict__ bias,  // [256]
                 float* __restrict__ emb_out,     // d_out region
                 int xnode_off)                   // offset into g_x (node index)
{
    constexpr int RPW  = 4;
    constexpr int ROWS = 32;       // 8 warps * 4 rows

    extern __shared__ float sm[];
    float* WhhT  = sm;                       // 64 * 257
    float* Wih_s = WhhT + 64 * 257;          // 256 * D
    float* b_s   = Wih_s + 256 * D;          // 256
    float* hsh   = b_s + 256;                // ROWS * 64
    float* xs    = hsh + ROWS * 64;          // ROWS * T * D

    const int tid  = threadIdx.x;
    const int base = blockIdx.x * ROWS;

    for (int idx = tid; idx < 256 * 64; idx += 256) {
        int j = idx >> 6, k = idx & 63;
        WhhT[k * 257 + j] = Whh[idx];
    }
    for (int idx = tid; idx < 256 * D; idx += 256) Wih_s[idx] = Wih[idx];
    b_s[tid] = bias[tid];
    for (int idx = tid; idx < ROWS * T * D; idx += 256)
        xs[idx] = xin[(size_t)base * (T * D) + idx];
    for (int idx = tid; idx < ROWS * 64; idx += 256) hsh[idx] = 0.0f;
    __syncthreads();

    const int warp = tid >> 5, lane = tid & 31;
    const int r0 = warp * RPW;

    float c[RPW][2];
    float hm[RPW][2];
#pragma unroll
    for (int r = 0; r < RPW; ++r) {
        c[r][0] = c[r][1] = 0.0f;
        hm[r][0] = hm[r][1] = 0.0f;
    }

#pragma unroll 1
    for (int t = 0; t < T; ++t) {
        float acc[RPW][8];
        // acc = b + Wih @ x_t
#pragma unroll
        for (int i = 0; i < 8; ++i) {
            int j = lane + 32 * i;
            float bj = b_s[j];
            float wd[D];
#pragma unroll
            for (int d = 0; d < D; ++d) wd[d] = Wih_s[j * D + d];
#pragma unroll
            for (int r = 0; r < RPW; ++r) {
                float a = bj;
#pragma unroll
                for (int d = 0; d < D; ++d)
                    a = fmaf(wd[d], xs[(r0 + r) * (T * D) + t * D + d], a);
                acc[r][i] = a;
            }
        }
        // acc += h @ Whh^T
#pragma unroll 8
        for (int k = 0; k < 64; ++k) {
            float w[8];
#pragma unroll
            for (int i = 0; i < 8; ++i) w[i] = WhhT[k * 257 + lane + 32 * i];
#pragma unroll
            for (int r = 0; r < RPW; ++r) {
                float hk = hsh[(r0 + r) * 64 + k];
#pragma unroll
                for (int i = 0; i < 8; ++i) acc[r][i] = fmaf(w[i], hk, acc[r][i]);
            }
        }
        __syncwarp();
        // gates: thread owns h indices lane, lane+32 per row
#pragma unroll
        for (int r = 0; r < RPW; ++r) {
#pragma unroll
            for (int m = 0; m < 2; ++m) {
                float ig = sigmoidf_(acc[r][m]);
                float fg = sigmoidf_(acc[r][2 + m]);
                float gg = tanhf_(acc[r][4 + m]);
                float og = sigmoidf_(acc[r][6 + m]);
                float cn = fmaf(fg, c[r][m], ig * gg);
                c[r][m]  = cn;
                float hv = og * tanhf_(cn);
                hsh[(r0 + r) * 64 + lane + 32 * m] = hv;
                if (MEAN) hm[r][m] += hv;
            }
        }
        __syncwarp();
    }

#pragma unroll
    for (int r = 0; r < RPW; ++r) {
        int row = base + r0 + r;
#pragma unroll
        for (int m = 0; m < 2; ++m) {
            int col = lane + 32 * m;
            float v = MEAN ? hm[r][m] * (1.0f / T) : hsh[(r0 + r) * 64 + col];
            emb_out[(size_t)row * 64 + col]            = v;
            g_x[(size_t)(xnode_off + row) * 64 + col]  = v;
        }
    }
}

// ---------------------------------------------------------------------------
// init: deg = 1 (self loop weight), stats = 0
// ---------------------------------------------------------------------------
__global__ void init_kernel() {
    int i = blockIdx.x * blockDim.x + threadIdx.x;
    if (i < N_TOT) g_deg[i] = 1.0f;
    if (i < 256) g_stats[i] = 0.0f;
}

// ---------------------------------------------------------------------------
// degree accumulation over all directed edges
// ---------------------------------------------------------------------------
__global__ void deg_kernel(const int* __restrict__ aa_src, const int* __restrict__ aa_dst,
                           const float* __restrict__ len_aa,
                           const int* __restrict__ al_a, const int* __restrict__ al_l,
                           const float* __restrict__ len_al,
                           const float* __restrict__ w_e, const float* __restrict__ b_e) {
    int e = blockIdx.x * blockDim.x + threadIdx.x;
    if (e >= ETOT) return;
    float we = w_e[0], be = b_e[0];
    int dst; float len;
    if (e < E_AA) {
        dst = aa_dst[e]; len = len_aa[e];
    } else if (e < E_AA + E_AL) {
        int i = e - E_AA; dst = A_TOT + al_l[i]; len = len_al[i];
    } else {
        int i = e - E_AA - E_AL; dst = al_a[i]; len = len_al[i];
    }
    float w = sigmoidf_(fmaf(len, we, be));
    atomicAdd(&g_deg[dst], w);
}

__global__ void dinv_kernel() {
    int i = blockIdx.x * blockDim.x + threadIdx.x;
    if (i >= N_TOT) return;
    float d = g_deg[i];
    g_dinv[i] = (d > 0.0f) ? rsqrtf(d) : 0.0f;
}

// ---------------------------------------------------------------------------
// lin kernel: g_h = act(in) @ W ;  act = identity or BN+ReLU (from g_stats)
// in_sel: 0 -> g_x, 1 -> g_out1
// ---------------------------------------------------------------------------
__global__ __launch_bounds__(256)
void lin_kernel(const float* __restrict__ W, int in_sel, int use_bn) {
    __shared__ float Ws[64 * 65];
    __shared__ float xsh[64 * 65];
    const float* in = in_sel ? g_out1 : g_x;

    int tid = threadIdx.x;
    for (int idx = tid; idx < 64 * 64; idx += 256) {
        int k = idx >> 6, j = idx & 63;
        Ws[k * 65 + j] = W[idx];
    }
    int base = blockIdx.x * 64;
    for (int idx = tid; idx < 64 * 64; idx += 256) {
        int r = idx >> 6, k = idx & 63;
        int row = base + r;
        float v = (row < N_TOT) ? in[(size_t)row * 64 + k] : 0.0f;
        if (use_bn) v = fmaxf(fmaf(v, g_stats[128 + k], g_stats[192 + k]), 0.0f);
        xsh[r * 65 + k] = v;
    }
    __syncthreads();

    int j = tid & 63, rl = tid >> 6;
    for (int rr = rl; rr < 64; rr += 4) {
        float a = 0.0f;
#pragma unroll
        for (int k = 0; k < 64; ++k) a = fmaf(xsh[rr * 65 + k], Ws[k * 65 + j], a);
        int row = base + rr;
        if (row < N_TOT) g_h[(size_t)row * 64 + j] = a;
    }
}

// ---------------------------------------------------------------------------
// init_out: out[n] = b + h[n] * dinv[n]^2  (self-loop term + bias)
// map==0 -> g_out1 ; map==1 -> scattered into d_out regions
// ---------------------------------------------------------------------------
__global__ void init_out_kernel(const float* __restrict__ bvec, float* __restrict__ dout, int map) {
    int idx = blockIdx.x * blockDim.x + threadIdx.x;
    if (idx >= N_TOT * HDIM) return;
    int n = idx >> 6, j = idx & 63;
    float di = g_dinv[n];
    float v = fmaf(g_h[idx], di * di, bvec[j]);
    if (map) {
        size_t off = (n < A_TOT) ? ((size_t)(A_TOT + n) * 64)
                                 : ((size_t)(A_TOT + L_TOT + n) * 64);
        dout[off + j] = v;
    } else {
        g_out1[idx] = v;
    }
}

// ---------------------------------------------------------------------------
// agg kernel: 1 warp per directed edge; out[dst] += h[src] * norm(e)
// ---------------------------------------------------------------------------
__global__ __launch_bounds__(256)
void agg_kernel(const int* __restrict__ aa_src, const int* __restrict__ aa_dst,
                const float* __restrict__ len_aa,
                const int* __restrict__ al_a, const int* __restrict__ al_l,
                const float* __restrict__ len_al,
                const float* __restrict__ w_e, const float* __restrict__ b_e,
                float* __restrict__ dout, int map) {
    int e = blockIdx.x * 8 + (threadIdx.x >> 5);
    if (e >= ETOT) return;
    int lane = threadIdx.x & 31;

    int src, dst; float len;
    if (e < E_AA) {
        src = aa_src[e]; dst = aa_dst[e]; len = len_aa[e];
    } else if (e < E_AA + E_AL) {
        int i = e - E_AA; src = al_a[i]; dst = A_TOT + al_l[i]; len = len_al[i];
    } else {
        int i = e - E_AA - E_AL; src = A_TOT + al_l[i]; dst = al_a[i]; len = len_al[i];
    }
    float w = sigmoidf_(fmaf(len, w_e[0], b_e[0]));
    float nrm = g_dinv[src] * w * g_dinv[dst];

    float2 v = *(const float2*)(g_h + (size_t)src * 64 + lane * 2);
    float* op;
    if (map) {
        size_t off = (dst < A_TOT) ? ((size_t)(A_TOT + dst) * 64)
                                   : ((size_t)(A_TOT + L_TOT + dst) * 64);
        op = dout + off;
    } else {
        op = g_out1 + (size_t)dst * 64;
    }
    atomicAdd(op + lane * 2,     v.x * nrm);
    atomicAdd(op + lane * 2 + 1, v.y * nrm);
}

// ---------------------------------------------------------------------------
// BatchNorm stats: per-column sum / sumsq over g_out1
// ---------------------------------------------------------------------------
__global__ __launch_bounds__(256)
void bn_stats_kernel() {
    __shared__ float sh[512];
    int tid = threadIdx.x;
    int j = tid & 63;
    float s = 0.0f, s2 = 0.0f;
    for (int row = blockIdx.x * 4 + (tid >> 6); row < N_TOT; row += gridDim.x * 4) {
        float v = g_out1[(size_t)row * 64 + j];
        s += v; s2 += v * v;
    }
    sh[tid] = s; sh[256 + tid] = s2;
    __syncthreads();
    if (tid < 64) {
        float t = sh[tid] + sh[tid + 64] + sh[tid + 128] + sh[tid + 192];
        atomicAdd(&g_stats[tid], t);
    } else if (tid < 128) {
        int jj = tid - 64;
        float t = sh[256 + jj] + sh[256 + jj + 64] + sh[256 + jj + 128] + sh[256 + jj + 192];
        atomicAdd(&g_stats[64 + jj], t);
    }
}

__global__ void bn_final_kernel(const float* __restrict__ gamma, const float* __restrict__ beta) {
    int j = threadIdx.x;
    if (j >= 64) return;
    float mean = g_stats[j] * (1.0f / N_TOT);
    float var  = g_stats[64 + j] * (1.0f / N_TOT) - mean * mean;
    float rs   = rsqrtf(var + BN_EPS);
    float sc   = rs * gamma[j];
    g_stats[128 + j] = sc;
    g_stats[192 + j] = beta[j] - mean * sc;
}

// ---------------------------------------------------------------------------
// kernel_launch
// ---------------------------------------------------------------------------
extern "C" void kernel_launch(void* const* d_in, const int* in_sizes, int n_in,
                              void* d_out, int out_size) {
    const float* agent_hist = (const float*)d_in[0];
    const float* lane_nodes = (const float*)d_in[1];
    const int*   eaa        = (const int*)d_in[2];
    const float* len_aa     = (const float*)d_in[3];
    const int*   eal        = (const int*)d_in[4];
    const float* len_al     = (const float*)d_in[5];
    const float* Wih_a      = (const float*)d_in[6];
    const float* Whh_a      = (const float*)d_in[7];
    const float* b_a        = (const float*)d_in[8];
    const float* Wih_l      = (const float*)d_in[9];
    const float* Whh_l      = (const float*)d_in[10];
    const float* b_l        = (const float*)d_in[11];
    const float* w_e        = (const float*)d_in[12];
    const float* b_e        = (const float*)d_in[13];
    const float* W1         = (const float*)d_in[14];
    const float* b1         = (const float*)d_in[15];
    const float* gamma1     = (const float*)d_in[16];
    const float* beta1      = (const float*)d_in[17];
    const float* W2         = (const float*)d_in[18];
    const float* b2         = (const float*)d_in[19];
    float* out = (float*)d_out;

    const int* aa_src = eaa;
    const int* aa_dst = eaa + E_AA;
    const int* al_a   = eal;
    const int* al_l   = eal + E_AL;

    // dynamic smem sizes for the two LSTM instantiations
    const int smem_agent = (64 * 257 + 256 * 5 + 256 + 32 * 64 + 32 * 20 * 5) * 4;  // 92928 B
    const int smem_lane  = (64 * 257 + 256 * 2 + 256 + 32 * 64 + 32 * 10 * 2) * 4;  // 79616 B
    cudaFuncSetAttribute((const void*)lstm_kernel<20, 5, false>,
                         cudaFuncAttributeMaxDynamicSharedMemorySize, smem_agent);
    cudaFuncSetAttribute((const void*)lstm_kernel<10, 2, true>,
                         cudaFuncAttributeMaxDynamicSharedMemorySize, smem_lane);

    // 1-2. LSTMs: agent_emb -> out[0 : A*64] and g_x[0:A]; lane_emb -> out[2A*64 : ...] and g_x[A:]
    lstm_kernel<20, 5, false><<<A_TOT / 32, 256, smem_agent>>>(
        agent_hist, Wih_a, Whh_a, b_a, out, 0);
    lstm_kernel<10, 2, true><<<L_TOT / 32, 256, smem_lane>>>(
        lane_nodes, Wih_l, Whh_l, b_l, out + (size_t)2 * A_TOT * 64, A_TOT);

    // 3. deg = 1, stats = 0
    init_kernel<<<(N_TOT + 255) / 256, 256>>>();

    // 4. degree accumulation
    deg_kernel<<<(ETOT + 255) / 256, 256>>>(aa_src, aa_dst, len_aa, al_a, al_l, len_al, w_e, b_e);

    // 5. dinv
    dinv_kernel<<<(N_TOT + 255) / 256, 256>>>();

    // 6. lin1: g_h = g_x @ W1
    lin_kernel<<<(N_TOT + 63) / 64, 256>>>(W1, /*in_sel=*/0, /*use_bn=*/0);

    // 7. conv1 init: g_out1 = b1 + self-loop
    init_out_kernel<<<(N_TOT * HDIM + 255) / 256, 256>>>(b1, out, /*map=*/0);

    // 8. conv1 aggregate
    agg_kernel<<<ETOT / 8, 256>>>(aa_src, aa_dst, len_aa, al_a, al_l, len_al, w_e, b_e,
                                  out, /*map=*/0);

    // 9-10. batchnorm stats + finalize
    bn_stats_kernel<<<512, 256>>>();
    bn_final_kernel<<<1, 64>>>(gamma1, beta1);

    // 11. lin2: g_h = relu(bn(g_out1)) @ W2
    lin_kernel<<<(N_TOT + 63) / 64, 256>>>(W2, /*in_sel=*/1, /*use_bn=*/1);

    // 12. conv2 init directly into d_out regions
    init_out_kernel<<<(N_TOT * HDIM + 255) / 256, 256>>>(b2, out, /*map=*/1);

    // 13. conv2 aggregate into d_out regions
    agg_kernel<<<ETOT / 8, 256>>>(aa_src, aa_dst, len_aa, al_a, al_l, len_al, w_e, b_e,
                                  out, /*map=*/1);
}

// round 3
// speedup vs baseline: 1.0013x; 1.0013x over previous
#include <cuda_runtime.h>
#include <cuda_bf16.h>
#include <cstdint>

// ---------------------------------------------------------------------------
// Problem constants
// ---------------------------------------------------------------------------
#define A_TOT 20000
#define L_TOT 80000
#define N_TOT 100000
#define E_AA  400000
#define E_AL  800000
#define ETOT  (E_AA + 2 * E_AL)
#define HDIM  64
#define BN_EPS 1e-5f

typedef unsigned long long u64;

// ---------------------------------------------------------------------------
// Scratch (device globals)
// ---------------------------------------------------------------------------
__device__ float g_x[N_TOT * HDIM];
__device__ float g_h[N_TOT * HDIM];
__device__ float g_out1[N_TOT * HDIM];
__device__ float g_deg[N_TOT];
__device__ float g_dinv[N_TOT];
__device__ float g_stats[256];

// ---------------------------------------------------------------------------
// helpers
// ---------------------------------------------------------------------------
__device__ __forceinline__ float sigmoidf_(float x) {
    return 1.0f / (1.0f + __expf(-x));
}
__device__ __forceinline__ float tanhf_(float x) {
    return 2.0f / (1.0f + __expf(-2.0f * x)) - 1.0f;
}
__device__ __forceinline__ u64 ffma2(u64 a, u64 b, u64 c) {
    u64 d;
    asm("fma.rn.f32x2 %0, %1, %2, %3;" : "=l"(d) : "l"(a), "l"(b), "l"(c));
    return d;
}
__device__ __forceinline__ u64 pack2(float x, float y) {
    u64 d; asm("mov.b64 %0, {%1, %2};" : "=l"(d) : "f"(x), "f"(y)); return d;
}
__device__ __forceinline__ float2 unpack2(u64 v) {
    float2 r; asm("mov.b64 {%0, %1}, %2;" : "=f"(r.x), "=f"(r.y) : "l"(v)); return r;
}

// ---------------------------------------------------------------------------
// LSTM kernel (f32x2 packed math)
//   block: 256 thr = 8 warps, 64 rows (8 rows per warp)
//   thread owns hidden units u0=2*lane, u1=2*lane+1 across its 8 rows
//   gate columns j = g*64 + 2*lane + m  (g: 0=i,1=f,2=g,3=o)
//   WhhT  [64k][258]  : WhhT[k*258 + j] = Whh[j*64+k]  (pairs 8B aligned)
//   hshD  [64r][128]  : duplicated pairs (h_k, h_k) at offset 2k
// ---------------------------------------------------------------------------
template <int T, int D, bool MEAN>
__global__ __launch_bounds__(256, 1)
void lstm_kernel(const float* __restrict__ xin,
                 const float* __restrict__ Wih,
                 const float* __restrict__ Whh,
                 const float* __restrict__ bias,
                 float* __restrict__ emb_out,
                 int xnode_off, int nrows)
{
    constexpr int ROWS = 64;
    constexpr int RPW  = 8;
    constexpr int TD   = T * D;

    extern __shared__ float sm[];
    float* WhhT = sm;                     // 64*258 = 16512
    float* hshD = WhhT + 64 * 258;        // 64*128 = 8192
    float* WihT = hshD + ROWS * 128;      // D*256
    float* b_s  = WihT + D * 256;         // 256
    float* xs   = b_s + 256;              // ROWS*T*D

    const int tid  = threadIdx.x;
    const int base = blockIdx.x * ROWS;

    for (int idx = tid; idx < 256 * 64; idx += 256) {
        int j = idx >> 6, k = idx & 63;
        WhhT[k * 258 + j] = Whh[idx];
    }
    for (int idx = tid; idx < 256 * D; idx += 256) {
        int j = idx / D, d = idx - j * D;
        WihT[d * 256 + j] = Wih[idx];
    }
    b_s[tid] = bias[tid];
    for (int idx = tid; idx < ROWS * TD; idx += 256) {
        int r = idx / TD;
        xs[idx] = (base + r < nrows) ? xin[(size_t)base * TD + idx] : 0.0f;
    }
    for (int idx = tid; idx < ROWS * 128; idx += 256) hshD[idx] = 0.0f;
    __syncthreads();

    const int warp = tid >> 5, lane = tid & 31;
    const int r0 = warp * RPW;

    float c[RPW][2];
    float hm[RPW][2];
#pragma unroll
    for (int r = 0; r < RPW; ++r) {
        c[r][0] = c[r][1] = 0.0f;
        hm[r][0] = hm[r][1] = 0.0f;
    }

#pragma unroll 1
    for (int t = 0; t < T; ++t) {
        u64 acc[RPW][4];
        // acc = b
        {
            u64 bb[4];
#pragma unroll
            for (int g = 0; g < 4; ++g)
                bb[g] = *(const u64*)&b_s[g * 64 + 2 * lane];
#pragma unroll
            for (int r = 0; r < RPW; ++r)
#pragma unroll
                for (int g = 0; g < 4; ++g) acc[r][g] = bb[g];
        }
        // acc += Wih @ x_t
#pragma unroll
        for (int d = 0; d < D; ++d) {
            u64 wv[4];
#pragma unroll
            for (int g = 0; g < 4; ++g)
                wv[g] = *(const u64*)&WihT[d * 256 + g * 64 + 2 * lane];
#pragma unroll
            for (int r = 0; r < RPW; ++r) {
                float xv = xs[(r0 + r) * TD + t * D + d];
                u64 x2 = pack2(xv, xv);
#pragma unroll
                for (int g = 0; g < 4; ++g) acc[r][g] = ffma2(wv[g], x2, acc[r][g]);
            }
        }
        // acc += h @ Whh^T   (skip at t==0: h is zero)
        if (t > 0) {
#pragma unroll 4
            for (int k = 0; k < 64; ++k) {
                u64 w0 = *(const u64*)&WhhT[k * 258 +   0 + 2 * lane];
                u64 w1 = *(const u64*)&WhhT[k * 258 +  64 + 2 * lane];
                u64 w2 = *(const u64*)&WhhT[k * 258 + 128 + 2 * lane];
                u64 w3 = *(const u64*)&WhhT[k * 258 + 192 + 2 * lane];
#pragma unroll
                for (int r = 0; r < RPW; ++r) {
                    u64 h2 = *(const u64*)&hshD[(r0 + r) * 128 + 2 * k];
                    acc[r][0] = ffma2(w0, h2, acc[r][0]);
                    acc[r][1] = ffma2(w1, h2, acc[r][1]);
                    acc[r][2] = ffma2(w2, h2, acc[r][2]);
                    acc[r][3] = ffma2(w3, h2, acc[r][3]);
                }
            }
        }
        __syncwarp();
        // gates
#pragma unroll
        for (int r = 0; r < RPW; ++r) {
            float2 gi = unpack2(acc[r][0]);
            float2 gf = unpack2(acc[r][1]);
            float2 gg = unpack2(acc[r][2]);
            float2 go = unpack2(acc[r][3]);

            float i0 = sigmoidf_(gi.x), i1 = sigmoidf_(gi.y);
            float f0 = sigmoidf_(gf.x), f1 = sigmoidf_(gf.y);
            float t0 = tanhf_(gg.x),    t1 = tanhf_(gg.y);
            float o0 = sigmoidf_(go.x), o1 = sigmoidf_(go.y);

            float c0 = fmaf(f0, c[r][0], i0 * t0);
            float c1 = fmaf(f1, c[r][1], i1 * t1);
            c[r][0] = c0; c[r][1] = c1;
            float h0 = o0 * tanhf_(c0);
            float h1 = o1 * tanhf_(c1);
            if (MEAN) { hm[r][0] += h0; hm[r][1] += h1; }
            // duplicated pairs (h0,h0,h1,h1) at float offset 4*lane
            *(float4*)&hshD[(r0 + r) * 128 + 4 * lane] = make_float4(h0, h0, h1, h1);
        }
        __syncwarp();
    }

#pragma unroll
    for (int r = 0; r < RPW; ++r) {
        int row = base + r0 + r;
        if (row >= nrows) continue;
        float2 v;
        if (MEAN) {
            v.x = hm[r][0] * (1.0f / T);
            v.y = hm[r][1] * (1.0f / T);
        } else {
            v.x = hshD[(r0 + r) * 128 + 4 * lane];
            v.y = hshD[(r0 + r) * 128 + 4 * lane + 2];
        }
        *(float2*)&emb_out[(size_t)row * 64 + 2 * lane]           = v;
        *(float2*)&g_x[(size_t)(xnode_off + row) * 64 + 2 * lane] = v;
    }
}

// ---------------------------------------------------------------------------
__global__ void init_kernel() {
    int i = blockIdx.x * blockDim.x + threadIdx.x;
    if (i < N_TOT) g_deg[i] = 1.0f;
    if (i < 256) g_stats[i] = 0.0f;
}

__global__ void deg_kernel(const int* __restrict__ aa_src, const int* __restrict__ aa_dst,
                           const float* __restrict__ len_aa,
                           const int* __restrict__ al_a, const int* __restrict__ al_l,
                           const float* __restrict__ len_al,
                           const float* __restrict__ w_e, const float* __restrict__ b_e) {
    int e = blockIdx.x * blockDim.x + threadIdx.x;
    if (e >= ETOT) return;
    float we = w_e[0], be = b_e[0];
    int dst; float len;
    if (e < E_AA) {
        dst = aa_dst[e]; len = len_aa[e];
    } else if (e < E_AA + E_AL) {
        int i = e - E_AA; dst = A_TOT + al_l[i]; len = len_al[i];
    } else {
        int i = e - E_AA - E_AL; dst = al_a[i]; len = len_al[i];
    }
    float w = sigmoidf_(fmaf(len, we, be));
    atomicAdd(&g_deg[dst], w);
}

__global__ void dinv_kernel() {
    int i = blockIdx.x * blockDim.x + threadIdx.x;
    if (i >= N_TOT) return;
    float d = g_deg[i];
    g_dinv[i] = (d > 0.0f) ? rsqrtf(d) : 0.0f;
}

// ---------------------------------------------------------------------------
__global__ __launch_bounds__(256)
void lin_kernel(const float* __restrict__ W, int in_sel, int use_bn) {
    __shared__ float Ws[64 * 65];
    __shared__ float xsh[64 * 65];
    const float* in = in_sel ? g_out1 : g_x;

    int tid = threadIdx.x;
    for (int idx = tid; idx < 64 * 64; idx += 256) {
        int k = idx >> 6, j = idx & 63;
        Ws[k * 65 + j] = W[idx];
    }
    int base = blockIdx.x * 64;
    for (int idx = tid; idx < 64 * 64; idx += 256) {
        int r = idx >> 6, k = idx & 63;
        int row = base + r;
        float v = (row < N_TOT) ? in[(size_t)row * 64 + k] : 0.0f;
        if (use_bn) v = fmaxf(fmaf(v, g_stats[128 + k], g_stats[192 + k]), 0.0f);
        xsh[r * 65 + k] = v;
    }
    __syncthreads();

    int j = tid & 63, rl = tid >> 6;
    for (int rr = rl; rr < 64; rr += 4) {
        float a = 0.0f;
#pragma unroll
        for (int k = 0; k < 64; ++k) a = fmaf(xsh[rr * 65 + k], Ws[k * 65 + j], a);
        int row = base + rr;
        if (row < N_TOT) g_h[(size_t)row * 64 + j] = a;
    }
}

// ---------------------------------------------------------------------------
__global__ void init_out_kernel(const float* __restrict__ bvec, float* __restrict__ dout, int map) {
    int idx = blockIdx.x * blockDim.x + threadIdx.x;
    if (idx >= N_TOT * HDIM) return;
    int n = idx >> 6, j = idx & 63;
    float di = g_dinv[n];
    float v = fmaf(g_h[idx], di * di, bvec[j]);
    if (map) {
        size_t off = (n < A_TOT) ? ((size_t)(A_TOT + n) * 64)
                                 : ((size_t)(A_TOT + L_TOT + n) * 64);
        dout[off + j] = v;
    } else {
        g_out1[idx] = v;
    }
}

// ---------------------------------------------------------------------------
// agg: 16 lanes per edge, vector red.global.add.v4.f32
// ---------------------------------------------------------------------------
__global__ __launch_bounds__(256)
void agg_kernel(const int* __restrict__ aa_src, const int* __restrict__ aa_dst,
                const float* __restrict__ len_aa,
                const int* __restrict__ al_a, const int* __restrict__ al_l,
                const float* __restrict__ len_al,
                const float* __restrict__ w_e, const float* __restrict__ b_e,
                float* __restrict__ dout, int map) {
    int e = blockIdx.x * 16 + (threadIdx.x >> 4);
    if (e >= ETOT) return;
    int l = threadIdx.x & 15;

    int src, dst; float len;
    if (e < E_AA) {
        src = aa_src[e]; dst = aa_dst[e]; len = len_aa[e];
    } else if (e < E_AA + E_AL) {
        int i = e - E_AA; src = al_a[i]; dst = A_TOT + al_l[i]; len = len_al[i];
    } else {
        int i = e - E_AA - E_AL; src = A_TOT + al_l[i]; dst = al_a[i]; len = len_al[i];
    }
    float w = sigmoidf_(fmaf(len, w_e[0], b_e[0]));
    float nrm = g_dinv[src] * w * g_dinv[dst];

    float4 v = *(const float4*)(g_h + (size_t)src * 64 + l * 4);
    float* op;
    if (map) {
        size_t off = (dst < A_TOT) ? ((size_t)(A_TOT + dst) * 64)
                                   : ((size_t)(A_TOT + L_TOT + dst) * 64);
        op = dout + off + l * 4;
    } else {
        op = g_out1 + (size_t)dst * 64 + l * 4;
    }
    asm volatile("red.global.add.v4.f32 [%0], {%1, %2, %3, %4};"
                 :: "l"(op), "f"(v.x * nrm), "f"(v.y * nrm),
                    "f"(v.z * nrm), "f"(v.w * nrm)
                 : "memory");
}

// ---------------------------------------------------------------------------
__global__ __launch_bounds__(256)
void bn_stats_kernel() {
    __shared__ float sh[512];
    int tid = threadIdx.x;
    int j = tid & 63;
    float s = 0.0f, s2 = 0.0f;
    for (int row = blockIdx.x * 4 + (tid >> 6); row < N_TOT; row += gridDim.x * 4) {
        float v = g_out1[(size_t)row * 64 + j];
        s += v; s2 += v * v;
    }
    sh[tid] = s; sh[256 + tid] = s2;
    __syncthreads();
    if (tid < 64) {
        float t = sh[tid] + sh[tid + 64] + sh[tid + 128] + sh[tid + 192];
        atomicAdd(&g_stats[tid], t);
    } else if (tid < 128) {
        int jj = tid - 64;
        float t = sh[256 + jj] + sh[256 + jj + 64] + sh[256 + jj + 128] + sh[256 + jj + 192];
        atomicAdd(&g_stats[64 + jj], t);
    }
}

__global__ void bn_final_kernel(const float* __restrict__ gamma, const float* __restrict__ beta) {
    int j = threadIdx.x;
    if (j >= 64) return;
    float mean = g_stats[j] * (1.0f / N_TOT);
    float var  = g_stats[64 + j] * (1.0f / N_TOT) - mean * mean;
    float rs   = rsqrtf(var + BN_EPS);
    float sc   = rs * gamma[j];
    g_stats[128 + j] = sc;
    g_stats[192 + j] = beta[j] - mean * sc;
}

// ---------------------------------------------------------------------------
extern "C" void kernel_launch(void* const* d_in, const int* in_sizes, int n_in,
                              void* d_out, int out_size) {
    const float* agent_hist = (const float*)d_in[0];
    const float* lane_nodes = (const float*)d_in[1];
    const int*   eaa        = (const int*)d_in[2];
    const float* len_aa     = (const float*)d_in[3];
    const int*   eal        = (const int*)d_in[4];
    const float* len_al     = (const float*)d_in[5];
    const float* Wih_a      = (const float*)d_in[6];
    const float* Whh_a      = (const float*)d_in[7];
    const float* b_a        = (const float*)d_in[8];
    const float* Wih_l      = (const float*)d_in[9];
    const float* Whh_l      = (const float*)d_in[10];
    const float* b_l        = (const float*)d_in[11];
    const float* w_e        = (const float*)d_in[12];
    const float* b_e        = (const float*)d_in[13];
    const float* W1         = (const float*)d_in[14];
    const float* b1         = (const float*)d_in[15];
    const float* gamma1     = (const float*)d_in[16];
    const float* beta1      = (const float*)d_in[17];
    const float* W2         = (const float*)d_in[18];
    const float* b2         = (const float*)d_in[19];
    float* out = (float*)d_out;

    const int* aa_src = eaa;
    const int* aa_dst = eaa + E_AA;
    const int* al_a   = eal;
    const int* al_l   = eal + E_AL;

    // dynamic smem: WhhT(16512) + hshD(8192) + WihT(256D) + b(256) + xs(64*T*D)
    const int smem_agent = (16512 + 8192 + 256 * 5 + 256 + 64 * 20 * 5) * 4;  // 127,040 B
    const int smem_lane  = (16512 + 8192 + 256 * 2 + 256 + 64 * 10 * 2) * 4;  //  107,008 B
    cudaFuncSetAttribute((const void*)lstm_kernel<20, 5, false>,
                         cudaFuncAttributeMaxDynamicSharedMemorySize, smem_agent);
    cudaFuncSetAttribute((const void*)lstm_kernel<10, 2, true>,
                         cudaFuncAttributeMaxDynamicSharedMemorySize, smem_lane);

    lstm_kernel<20, 5, false><<<(A_TOT + 63) / 64, 256, smem_agent>>>(
        agent_hist, Wih_a, Whh_a, b_a, out, 0, A_TOT);
    lstm_kernel<10, 2, true><<<(L_TOT + 63) / 64, 256, smem_lane>>>(
        lane_nodes, Wih_l, Whh_l, b_l, out + (size_t)2 * A_TOT * 64, A_TOT, L_TOT);

    init_kernel<<<(N_TOT + 255) / 256, 256>>>();
    deg_kernel<<<(ETOT + 255) / 256, 256>>>(aa_src, aa_dst, len_aa, al_a, al_l, len_al, w_e, b_e);
    dinv_kernel<<<(N_TOT + 255) / 256, 256>>>();

    lin_kernel<<<(N_TOT + 63) / 64, 256>>>(W1, 0, 0);
    init_out_kernel<<<(N_TOT * HDIM + 255) / 256, 256>>>(b1, out, 0);
    agg_kernel<<<(ETOT + 15) / 16, 256>>>(aa_src, aa_dst, len_aa, al_a, al_l, len_al, w_e, b_e,
                                          out, 0);

    bn_stats_kernel<<<512, 256>>>();
    bn_final_kernel<<<1, 64>>>(gamma1, beta1);

    lin_kernel<<<(N_TOT + 63) / 64, 256>>>(W2, 1, 1);
    init_out_kernel<<<(N_TOT * HDIM + 255) / 256, 256>>>(b2, out, 1);
    agg_kernel<<<(ETOT + 15) / 16, 256>>>(aa_src, aa_dst, len_aa, al_a, al_l, len_al, w_e, b_e,
                                          out, 1);
}